// round 13
// baseline (speedup 1.0000x reference)
#include <cuda_runtime.h>
#include <cstdint>

// ---------------------------------------------------------------------------
// Problem constants
//   B=32, T=2048, C=256, H=256, STRIDE=2, TC=1024, NC1=100, NC2=90
// ---------------------------------------------------------------------------
#define TCON 1024
typedef unsigned long long u64;

// ---- dual-direction LSTM smem (floats), per half: ----
//   sw   : 32 rows (8 j x 4 gates) x 256          = 8192
//   shh  : 32 b x 268 (pad, conflict-free)        = 8576
//   snew : 32 b x 8 j                             = 256
#define DH_SW_FLOATS 8192
#define DH_SHH_OFF   8192
#define DH_SN_OFF    (8192 + 8576)
#define DH_HALF_FLOATS 17024
#define DUAL_SMEM (2 * DH_HALF_FLOATS * 4)   // 136192 bytes

// ---------------------------------------------------------------------------
// Scratch (device globals; no runtime allocation allowed)
// ---------------------------------------------------------------------------
__device__ float g_y[32768 * 256];
__device__ float g_pre_f[33554432];     // 32768*1024
__device__ float g_pre_r[33554432];
__device__ float g_h0[16777216];        // 32768*512
__device__ float g_h1[16777216];
__device__ float g_fc_part[32 * 192 * 32];
// Monotone step counters, one 128B line each.
__device__ __align__(128) unsigned int g_cnt_f[32];
__device__ __align__(128) unsigned int g_cnt_r[32];
__device__ __align__(128) unsigned int g_ecnt[32];

// ---------------------------------------------------------------------------
// Helpers
// ---------------------------------------------------------------------------
__device__ __forceinline__ void fma2(u64& acc, u64 a, u64 b) {
    asm("fma.rn.f32x2 %0, %1, %2, %0;" : "+l"(acc) : "l"(a), "l"(b));
}
__device__ __forceinline__ float2 u2f2(u64 v) {
    float2 r;
    asm("mov.b64 {%0,%1}, %2;" : "=f"(r.x), "=f"(r.y) : "l"(v));
    return r;
}
__device__ __forceinline__ u64 dup2(float a) {
    u64 r;
    asm("mov.b64 %0, {%1,%1};" : "=l"(r) : "f"(a));
    return r;
}
__device__ __forceinline__ float sigf(float x) {
    return __fdividef(1.f, 1.f + __expf(-x));
}
__device__ __forceinline__ float tanh_fast(float x) {
    return 2.f * sigf(2.f * x) - 1.f;
}
__device__ __forceinline__ unsigned ld_acq(const unsigned* p) {
    unsigned v;
    asm volatile("ld.acquire.gpu.global.u32 %0, [%1];" : "=r"(v) : "l"(p) : "memory");
    return v;
}
__device__ __forceinline__ void st_rlx(unsigned* p, unsigned v) {
    asm volatile("st.relaxed.gpu.global.u32 [%0], %1;" :: "l"(p), "r"(v) : "memory");
}
__device__ __forceinline__ void red_rel_add(unsigned* p, unsigned v) {
    asm volatile("red.release.gpu.global.add.u32 [%0], %1;" :: "l"(p), "r"(v) : "memory");
}
__device__ __forceinline__ unsigned atom_inc_acqrel(unsigned* p) {
    unsigned o;
    asm volatile("atom.add.acq_rel.gpu.global.u32 %0, [%1], 1;" : "=r"(o) : "l"(p) : "memory");
    return o;
}
__device__ __forceinline__ void bar_named(int id, int cnt) {
    asm volatile("bar.sync %0, %1;" :: "r"(id), "r"(cnt) : "memory");
}

// ---------------------------------------------------------------------------
// Conv1d(k=3, stride=2, pad=1) + BN(affine, eval) + ReLU
// ---------------------------------------------------------------------------
__global__ void conv_bn(const float* __restrict__ x,
                        const float* __restrict__ cw,
                        const float* __restrict__ cb,
                        const float* __restrict__ gmm,
                        const float* __restrict__ bet,
                        const float* __restrict__ mean,
                        const float* __restrict__ var) {
    int tb = blockIdx.x;
    int t = tb >> 5, b = tb & 31;
    int c = threadIdx.x;
    float w0 = cw[c * 3 + 0], w1 = cw[c * 3 + 1], w2 = cw[c * 3 + 2];
    const float* xb = x + b * 2048;
    int xi = t * 2;
    float xm1 = (xi >= 1) ? xb[xi - 1] : 0.f;
    float x0 = xb[xi];
    float xp1 = xb[xi + 1];
    float conv = fmaf(xm1, w0, fmaf(x0, w1, xp1 * w2)) + cb[c];
    float inv = gmm[c] * rsqrtf(var[c] + 1e-5f);
    float v = conv * inv + (bet[c] - mean[c] * inv);
    g_y[(size_t)tb * 256 + c] = fmaxf(v, 0.f);
}

// ---------------------------------------------------------------------------
// SGEMM (TN): C[M=32768][N=1024] = A[M][K] * B[N][K]^T + bias[N]
// 128x128 block tile, BK=8, 256 threads, 8x8 micro-tile, f32x2-packed FMAs.
// ---------------------------------------------------------------------------
__global__ void __launch_bounds__(256) sgemm_tn(const float* __restrict__ A,
                                                const float* __restrict__ B,
                                                const float* __restrict__ bias,
                                                float* __restrict__ C,
                                                int K) {
    __shared__ __align__(16) float As[8][132];
    __shared__ __align__(16) float Bs[8][132];
    int bm = blockIdx.y * 128;
    int bn = blockIdx.x * 128;
    int tid = threadIdx.x;
    int tx = tid & 15, ty = tid >> 4;
    int lrow = tid >> 1;
    int lk = (tid & 1) * 4;
    const float* Ap = A + (size_t)(bm + lrow) * K + lk;
    const float* Bp = B + (size_t)(bn + lrow) * K + lk;

    u64 acc2[8][4];
#pragma unroll
    for (int i = 0; i < 8; i++)
#pragma unroll
        for (int j = 0; j < 4; j++) acc2[i][j] = 0ull;

    for (int k0 = 0; k0 < K; k0 += 8) {
        float4 av = *(const float4*)(Ap + k0);
        float4 bv = *(const float4*)(Bp + k0);
        __syncthreads();
        As[lk + 0][lrow] = av.x; As[lk + 1][lrow] = av.y;
        As[lk + 2][lrow] = av.z; As[lk + 3][lrow] = av.w;
        Bs[lk + 0][lrow] = bv.x; Bs[lk + 1][lrow] = bv.y;
        Bs[lk + 2][lrow] = bv.z; Bs[lk + 3][lrow] = bv.w;
        __syncthreads();
#pragma unroll
        for (int kk = 0; kk < 8; kk++) {
            float a[8];
            *(float4*)&a[0] = *(const float4*)&As[kk][ty * 8];
            *(float4*)&a[4] = *(const float4*)&As[kk][ty * 8 + 4];
            ulonglong2 bl = *(const ulonglong2*)&Bs[kk][tx * 8];
            ulonglong2 bh = *(const ulonglong2*)&Bs[kk][tx * 8 + 4];
            u64 b2[4] = {bl.x, bl.y, bh.x, bh.y};
#pragma unroll
            for (int i = 0; i < 8; i++) {
                u64 a2 = dup2(a[i]);
#pragma unroll
                for (int j2 = 0; j2 < 4; j2++) fma2(acc2[i][j2], a2, b2[j2]);
            }
        }
    }
#pragma unroll
    for (int i = 0; i < 8; i++) {
        size_t m = (size_t)(bm + ty * 8 + i);
        int n = bn + tx * 8;
        float2 p0 = u2f2(acc2[i][0]);
        float2 p1 = u2f2(acc2[i][1]);
        float2 p2 = u2f2(acc2[i][2]);
        float2 p3 = u2f2(acc2[i][3]);
        float4 o0, o1;
        o0.x = p0.x + bias[n + 0]; o0.y = p0.y + bias[n + 1];
        o0.z = p1.x + bias[n + 2]; o0.w = p1.y + bias[n + 3];
        o1.x = p2.x + bias[n + 4]; o1.y = p2.y + bias[n + 5];
        o1.z = p3.x + bias[n + 6]; o1.w = p3.y + bias[n + 7];
        *(float4*)&C[m * 1024 + n] = o0;
        *(float4*)&C[m * 1024 + n + 4] = o1;
    }
}

// ---------------------------------------------------------------------------
// BiLSTM recurrence, dual-direction co-resident version.
// 32 blocks x 512 threads. Threads [0,256): forward half, [256,512): reverse.
// Each half owns j-slice [jg*8, jg*8+8) for its direction:
//   warp jj (0..7) = local j, lane = batch (0..31),
//   per thread: 4 gates x 256 k, k-paired fma.rn.f32x2 (512 fma2).
// Halves are fully independent; they sync via SEPARATE named barriers
// (bar.sync 1 / bar.sync 2, 256 threads each) and separate global monotone
// counters (32 arrivals per direction). While one half sits in its
// store->red->poll->repack L2 latency chain, the other half's FFMA2 stream
// keeps the SMSPs issuing (2 warps/SMSP).
// ---------------------------------------------------------------------------
__global__ void __launch_bounds__(512, 1) lstm_dual(const float* __restrict__ pre_fw,
                                                    const float* __restrict__ pre_rv,
                                                    const float* __restrict__ whh_fw,
                                                    const float* __restrict__ whh_rv,
                                                    float* __restrict__ hout) {
    extern __shared__ float smem[];
    const int tid = threadIdx.x;
    const int half = tid >> 8;             // 0 = fwd, 1 = rev
    const int tid2 = tid & 255;
    const int jg = blockIdx.x;             // 0..31: j base = jg*8
    const int jj = tid2 >> 5;              // warp-in-half = local j (0..7)
    const int lane = tid2 & 31;            // lane = batch
    const int j = jg * 8 + jj;
    const int dir = half;
    const float* whh = dir ? whh_rv : whh_fw;
    const float* pre = dir ? pre_rv : pre_fw;
    const int foff = dir ? 256 : 0;
    const int NB = 1 + half;               // named barrier id (1 or 2)

    float* hb   = smem + half * DH_HALF_FLOATS;
    float* sw   = hb;                      // [jj*4+g][256]
    float* shh  = hb + DH_SHH_OFF;         // [b][268]
    float* snew = hb + DH_SN_OFF;          // [b*8 + jj]

    // Load W_hh slice: sw[(jj*4+g)*256 + k] = whh[(g*256 + jg*8 + jj)*256 + k]
    for (int i = tid2; i < 8192; i += 256) {
        int row = i >> 8;                  // ljj*4+g  (0..31)
        int k = i & 255;
        int ljj = row >> 2, g = row & 3;
        sw[row * 256 + k] = whh[((size_t)(g * 256 + jg * 8 + ljj)) * 256 + k];
    }
    for (int i = tid2; i < 8576; i += 256) shh[i] = 0.f;
    __syncthreads();                       // one whole-block sync at init only

    const float* hrow = shh + lane * 268;
    const float* wbase = sw + jj * 1024;   // rows jj*4 .. jj*4+3

    unsigned* cntp = dir ? &g_cnt_r[0] : &g_cnt_f[0];

    float c_state = 0.f;
    int t = dir ? (TCON - 1) : 0;

    // prefetch pre-activations for step 0
    const float* pr0 = pre + ((size_t)t * 32 + lane) * 1024 + j;
    float p_i = pr0[0], p_f = pr0[256], p_g = pr0[512], p_o = pr0[768];

    for (int step = 0; step < TCON; step++) {
        // ---- gate GEMV: acc[g] = sum_k W[g*256+j][k] * h[k][b] ----
        u64 a0 = 0ull, a1 = 0ull, a2 = 0ull, a3 = 0ull;
#pragma unroll 2
        for (int k4 = 0; k4 < 64; k4++) {
            ulonglong2 hv = *(const ulonglong2*)(hrow + k4 * 4);
            ulonglong2 w0 = *(const ulonglong2*)(wbase + k4 * 4);
            ulonglong2 w1 = *(const ulonglong2*)(wbase + 256 + k4 * 4);
            ulonglong2 w2 = *(const ulonglong2*)(wbase + 512 + k4 * 4);
            ulonglong2 w3 = *(const ulonglong2*)(wbase + 768 + k4 * 4);
            fma2(a0, w0.x, hv.x); fma2(a0, w0.y, hv.y);
            fma2(a1, w1.x, hv.x); fma2(a1, w1.y, hv.y);
            fma2(a2, w2.x, hv.x); fma2(a2, w2.y, hv.y);
            fma2(a3, w3.x, hv.x); fma2(a3, w3.y, hv.y);
        }
        float2 vi = u2f2(a0), vf = u2f2(a1), vg = u2f2(a2), vo = u2f2(a3);
        float gi = vi.x + vi.y + p_i;
        float gf = vf.x + vf.y + p_f;
        float gg = vg.x + vg.y + p_g;
        float go = vo.x + vo.y + p_o;
        float iv = sigf(gi), fv = sigf(gf), zv = tanh_fast(gg), ov = sigf(go);
        c_state = fv * c_state + iv * zv;
        float h_val = ov * tanh_fast(c_state);

        // stage h for the coalesced writer: snew[b][8j]
        snew[lane * 8 + jj] = h_val;

        int t_next = dir ? (t - 1) : (t + 1);
        if (step != TCON - 1) {
            // prefetch next step's pre-activations (independent of barrier)
            const float* prn = pre + ((size_t)t_next * 32 + lane) * 1024 + j;
            p_i = prn[0]; p_f = prn[256]; p_g = prn[512]; p_o = prn[768];
        }

        bar_named(NB, 256);                // snew complete for this half

        // ---- coalesced h store (warp 0 of half): 2 STG.128 per lane ----
        if (jj == 0) {
            float4 v0 = *(const float4*)(snew + lane * 8);
            float4 v1 = *(const float4*)(snew + lane * 8 + 4);
            float* dst = &hout[((size_t)t * 32 + lane) * 512 + foff + jg * 8];
            *(float4*)dst = v0;
            *(float4*)(dst + 4) = v1;
            __syncwarp();
            if (lane == 0) {
                red_rel_add(cntp, 1u);     // publish stores; no return trip
                unsigned target = 32u * (unsigned)(step + 1);
                while (ld_acq(cntp) < target) {}
            }
        }
        bar_named(NB, 256);

        // ---- coalesced repack: warp jj loads batches jj*4..jj*4+3 ----
        if (step != TCON - 1) {
            const float* base = hout + ((size_t)t * 32) * 512 + foff;
            float4 tmp[8];
#pragma unroll
            for (int i = 0; i < 8; i++) {
                int b = jj * 4 + (i >> 1);
                int j0 = (i & 1) * 128 + lane * 4;
                tmp[i] = *(const float4*)(base + (size_t)b * 512 + j0);
            }
#pragma unroll
            for (int i = 0; i < 8; i++) {
                int b = jj * 4 + (i >> 1);
                int j0 = (i & 1) * 128 + lane * 4;
                *(float4*)(shh + b * 268 + j0) = tmp[i];
            }
        }
        bar_named(NB, 256);
        t = t_next;
    }

    // ---- epilogue: one-shot reset of counters (64 halves arrive) ----
    if (tid2 == 0) {
        unsigned old = atom_inc_acqrel(&g_ecnt[0]);
        if (old == 63u) {
            st_rlx(&g_cnt_f[0], 0u);
            st_rlx(&g_cnt_r[0], 0u);
            st_rlx(&g_ecnt[0], 0u);
        }
    }
}

// ---------------------------------------------------------------------------
// FC heads (split-k partials + deterministic reduce)
// ---------------------------------------------------------------------------
__global__ void __launch_bounds__(256) fc_main(const float* __restrict__ h,
                                               const float* __restrict__ w1,
                                               const float* __restrict__ w2) {
    extern __shared__ float sh[];
    int kc = blockIdx.x;
    int grp = blockIdx.y;
    int tid = threadIdx.x;
    int nl = tid >> 4, bb = tid & 15;
    int n = grp * 16 + nl;
    bool valid = (n < 190);
    const float* wrow = valid
        ? (n < 100 ? w1 + (size_t)n * 524288 : w2 + (size_t)(n - 100) * 524288)
        : w1;

    float ax = 0.f, ay = 0.f;
    for (int tt = 0; tt < 32; tt++) {
        int t = kc * 32 + tt;
        const float* slab = h + (size_t)t * 16384;
        __syncthreads();
        for (int i = tid; i < 4096; i += 256) {
            int b = i >> 7;
            int q = i & 127;
            float4 v = *(const float4*)&slab[b * 512 + q * 4];
            int bl = (b & 15) * 2 + (b >> 4);
            int f = q * 4;
            sh[(f + 0) * 32 + bl] = v.x;
            sh[(f + 1) * 32 + bl] = v.y;
            sh[(f + 2) * 32 + bl] = v.z;
            sh[(f + 3) * 32 + bl] = v.w;
        }
        __syncthreads();
        const float* wp = wrow + (size_t)t * 512;
#pragma unroll 4
        for (int f4 = 0; f4 < 128; f4++) {
            float4 wv = *(const float4*)(wp + f4 * 4);
            const float* s0 = sh + (f4 * 4) * 32 + bb * 2;
            float2 a0 = *(const float2*)(s0);
            float2 a1 = *(const float2*)(s0 + 32);
            float2 a2 = *(const float2*)(s0 + 64);
            float2 a3 = *(const float2*)(s0 + 96);
            ax = fmaf(wv.x, a0.x, ax); ay = fmaf(wv.x, a0.y, ay);
            ax = fmaf(wv.y, a1.x, ax); ay = fmaf(wv.y, a1.y, ay);
            ax = fmaf(wv.z, a2.x, ax); ay = fmaf(wv.z, a2.y, ay);
            ax = fmaf(wv.w, a3.x, ax); ay = fmaf(wv.w, a3.y, ay);
        }
    }
    if (valid) {
        g_fc_part[((size_t)kc * 192 + n) * 32 + bb] = ax;
        g_fc_part[((size_t)kc * 192 + n) * 32 + bb + 16] = ay;
    }
}

__global__ void fc_reduce(const float* __restrict__ b1,
                          const float* __restrict__ b2,
                          float* __restrict__ out) {
    int i = blockIdx.x * 256 + threadIdx.x;
    if (i >= 6080) return;
    int n = i >> 5;
    int b = i & 31;
    float s = (n < 100) ? b1[n] : b2[n - 100];
#pragma unroll
    for (int kc = 0; kc < 32; kc++)
        s += g_fc_part[((size_t)kc * 192 + n) * 32 + b];
    if (n < 100) out[b * 100 + n] = s;
    else out[3200 + b * 90 + (n - 100)] = s;
}

// ---------------------------------------------------------------------------
// Launch
// ---------------------------------------------------------------------------
extern "C" void kernel_launch(void* const* d_in, const int* in_sizes, int n_in,
                              void* d_out, int out_size) {
    const float* x       = (const float*)d_in[0];
    const float* conv_w  = (const float*)d_in[1];
    const float* conv_b  = (const float*)d_in[2];
    const float* bn_g    = (const float*)d_in[3];
    const float* bn_b    = (const float*)d_in[4];
    const float* bn_m    = (const float*)d_in[5];
    const float* bn_v    = (const float*)d_in[6];
    const float* w_ih_f0 = (const float*)d_in[7];
    const float* w_hh_f0 = (const float*)d_in[8];
    const float* b_f0    = (const float*)d_in[9];
    const float* w_ih_r0 = (const float*)d_in[10];
    const float* w_hh_r0 = (const float*)d_in[11];
    const float* b_r0    = (const float*)d_in[12];
    const float* w_ih_f1 = (const float*)d_in[13];
    const float* w_hh_f1 = (const float*)d_in[14];
    const float* b_f1    = (const float*)d_in[15];
    const float* w_ih_r1 = (const float*)d_in[16];
    const float* w_hh_r1 = (const float*)d_in[17];
    const float* b_r1    = (const float*)d_in[18];
    const float* fc1_w   = (const float*)d_in[19];
    const float* fc1_b   = (const float*)d_in[20];
    const float* fc2_w   = (const float*)d_in[21];
    const float* fc2_b   = (const float*)d_in[22];
    float* out = (float*)d_out;

    float *py, *ppf, *ppr, *ph0, *ph1;
    cudaGetSymbolAddress((void**)&py, g_y);
    cudaGetSymbolAddress((void**)&ppf, g_pre_f);
    cudaGetSymbolAddress((void**)&ppr, g_pre_r);
    cudaGetSymbolAddress((void**)&ph0, g_h0);
    cudaGetSymbolAddress((void**)&ph1, g_h1);

    cudaFuncSetAttribute(lstm_dual, cudaFuncAttributeMaxDynamicSharedMemorySize, DUAL_SMEM);
    cudaFuncSetAttribute(fc_main, cudaFuncAttributeMaxDynamicSharedMemorySize, 65536);

    // 1) conv + bn + relu
    conv_bn<<<32768, 256>>>(x, conv_w, conv_b, bn_g, bn_b, bn_m, bn_v);

    // 2) layer 0 input projections (K=256)
    dim3 gg(8, 256);
    sgemm_tn<<<gg, 256>>>(py, w_ih_f0, b_f0, ppf, 256);
    sgemm_tn<<<gg, 256>>>(py, w_ih_r0, b_r0, ppr, 256);

    // 3) layer 0 recurrence (dual-direction co-resident)
    lstm_dual<<<32, 512, DUAL_SMEM>>>(ppf, ppr, w_hh_f0, w_hh_r0, ph0);

    // 4) layer 1 input projections (K=512)
    sgemm_tn<<<gg, 256>>>(ph0, w_ih_f1, b_f1, ppf, 512);
    sgemm_tn<<<gg, 256>>>(ph0, w_ih_r1, b_r1, ppr, 512);

    // 5) layer 1 recurrence
    lstm_dual<<<32, 512, DUAL_SMEM>>>(ppf, ppr, w_hh_f1, w_hh_r1, ph1);

    // 6) FC heads
    dim3 fg(32, 12);
    fc_main<<<fg, 256, 65536>>>(ph1, fc1_w, fc2_w);
    fc_reduce<<<24, 256>>>(fc1_b, fc2_b, out);
}

// round 14
// speedup vs baseline: 1.5445x; 1.5445x over previous
#include <cuda_runtime.h>
#include <cstdint>

// ---------------------------------------------------------------------------
// Problem constants
//   B=32, T=2048, C=256, H=256, STRIDE=2, TC=1024, NC1=100, NC2=90
// ---------------------------------------------------------------------------
#define TCON 1024
typedef unsigned long long u64;

// LSTM smem: weights 16x256 = 4096 floats; h: 32x268 = 8576; stage: 128
#define LSTM_SW_FLOATS 4096
#define LSTM_SH_FLOATS (32 * 268)
#define LSTM_SN_OFF (LSTM_SW_FLOATS + LSTM_SH_FLOATS)
#define LSTM_SMEM ((LSTM_SW_FLOATS + LSTM_SH_FLOATS + 128) * 4)

// ---------------------------------------------------------------------------
// Scratch (device globals; no runtime allocation allowed)
// ---------------------------------------------------------------------------
__device__ float g_y[32768 * 256];
__device__ float g_pre_f[33554432];     // GEMM out, [t*32+b][1024]
__device__ float g_pre_r[33554432];
__device__ float g_pret_f[33554432];    // transposed, [t][1024][32]
__device__ float g_pret_r[33554432];
__device__ float g_h0[16777216];        // [t*32+b][512]
__device__ float g_h1[16777216];
__device__ float g_hx[2 * 2 * 256 * 32];  // [dir][parity][j][b] exchange
__device__ float g_fc_part[32 * 192 * 32];
// Monotone step counters, one 128B line each.
__device__ __align__(128) unsigned int g_cnt_f[32];
__device__ __align__(128) unsigned int g_cnt_r[32];
__device__ __align__(128) unsigned int g_ecnt[32];

// ---------------------------------------------------------------------------
// Helpers
// ---------------------------------------------------------------------------
__device__ __forceinline__ void fma2(u64& acc, u64 a, u64 b) {
    asm("fma.rn.f32x2 %0, %1, %2, %0;" : "+l"(acc) : "l"(a), "l"(b));
}
__device__ __forceinline__ float2 u2f2(u64 v) {
    float2 r;
    asm("mov.b64 {%0,%1}, %2;" : "=f"(r.x), "=f"(r.y) : "l"(v));
    return r;
}
__device__ __forceinline__ u64 dup2(float a) {
    u64 r;
    asm("mov.b64 %0, {%1,%1};" : "=l"(r) : "f"(a));
    return r;
}
__device__ __forceinline__ float sigf(float x) {
    return __fdividef(1.f, 1.f + __expf(-x));
}
__device__ __forceinline__ float tanh_fast(float x) {
    return 2.f * sigf(2.f * x) - 1.f;
}
__device__ __forceinline__ unsigned ld_acq(const unsigned* p) {
    unsigned v;
    asm volatile("ld.acquire.gpu.global.u32 %0, [%1];" : "=r"(v) : "l"(p) : "memory");
    return v;
}
__device__ __forceinline__ void st_rlx(unsigned* p, unsigned v) {
    asm volatile("st.relaxed.gpu.global.u32 [%0], %1;" :: "l"(p), "r"(v) : "memory");
}
__device__ __forceinline__ void red_rel_add(unsigned* p, unsigned v) {
    asm volatile("red.release.gpu.global.add.u32 [%0], %1;" :: "l"(p), "r"(v) : "memory");
}
__device__ __forceinline__ unsigned atom_inc_acqrel(unsigned* p) {
    unsigned o;
    asm volatile("atom.add.acq_rel.gpu.global.u32 %0, [%1], 1;" : "=r"(o) : "l"(p) : "memory");
    return o;
}

// ---------------------------------------------------------------------------
// Conv1d(k=3, stride=2, pad=1) + BN(affine, eval) + ReLU
// ---------------------------------------------------------------------------
__global__ void conv_bn(const float* __restrict__ x,
                        const float* __restrict__ cw,
                        const float* __restrict__ cb,
                        const float* __restrict__ gmm,
                        const float* __restrict__ bet,
                        const float* __restrict__ mean,
                        const float* __restrict__ var) {
    int tb = blockIdx.x;
    int t = tb >> 5, b = tb & 31;
    int c = threadIdx.x;
    float w0 = cw[c * 3 + 0], w1 = cw[c * 3 + 1], w2 = cw[c * 3 + 2];
    const float* xb = x + b * 2048;
    int xi = t * 2;
    float xm1 = (xi >= 1) ? xb[xi - 1] : 0.f;
    float x0 = xb[xi];
    float xp1 = xb[xi + 1];
    float conv = fmaf(xm1, w0, fmaf(x0, w1, xp1 * w2)) + cb[c];
    float inv = gmm[c] * rsqrtf(var[c] + 1e-5f);
    float v = conv * inv + (bet[c] - mean[c] * inv);
    g_y[(size_t)tb * 256 + c] = fmaxf(v, 0.f);
}

// ---------------------------------------------------------------------------
// SGEMM (TN): C[M=32768][N=1024] = A[M][K] * B[N][K]^T + bias[N]
// 128x128 block tile, BK=8, 256 threads, 8x8 micro-tile, f32x2-packed FMAs.
// ---------------------------------------------------------------------------
__global__ void __launch_bounds__(256) sgemm_tn(const float* __restrict__ A,
                                                const float* __restrict__ B,
                                                const float* __restrict__ bias,
                                                float* __restrict__ C,
                                                int K) {
    __shared__ __align__(16) float As[8][132];
    __shared__ __align__(16) float Bs[8][132];
    int bm = blockIdx.y * 128;
    int bn = blockIdx.x * 128;
    int tid = threadIdx.x;
    int tx = tid & 15, ty = tid >> 4;
    int lrow = tid >> 1;
    int lk = (tid & 1) * 4;
    const float* Ap = A + (size_t)(bm + lrow) * K + lk;
    const float* Bp = B + (size_t)(bn + lrow) * K + lk;

    u64 acc2[8][4];
#pragma unroll
    for (int i = 0; i < 8; i++)
#pragma unroll
        for (int j = 0; j < 4; j++) acc2[i][j] = 0ull;

    for (int k0 = 0; k0 < K; k0 += 8) {
        float4 av = *(const float4*)(Ap + k0);
        float4 bv = *(const float4*)(Bp + k0);
        __syncthreads();
        As[lk + 0][lrow] = av.x; As[lk + 1][lrow] = av.y;
        As[lk + 2][lrow] = av.z; As[lk + 3][lrow] = av.w;
        Bs[lk + 0][lrow] = bv.x; Bs[lk + 1][lrow] = bv.y;
        Bs[lk + 2][lrow] = bv.z; Bs[lk + 3][lrow] = bv.w;
        __syncthreads();
#pragma unroll
        for (int kk = 0; kk < 8; kk++) {
            float a[8];
            *(float4*)&a[0] = *(const float4*)&As[kk][ty * 8];
            *(float4*)&a[4] = *(const float4*)&As[kk][ty * 8 + 4];
            ulonglong2 bl = *(const ulonglong2*)&Bs[kk][tx * 8];
            ulonglong2 bh = *(const ulonglong2*)&Bs[kk][tx * 8 + 4];
            u64 b2[4] = {bl.x, bl.y, bh.x, bh.y};
#pragma unroll
            for (int i = 0; i < 8; i++) {
                u64 a2 = dup2(a[i]);
#pragma unroll
                for (int j2 = 0; j2 < 4; j2++) fma2(acc2[i][j2], a2, b2[j2]);
            }
        }
    }
#pragma unroll
    for (int i = 0; i < 8; i++) {
        size_t m = (size_t)(bm + ty * 8 + i);
        int n = bn + tx * 8;
        float2 p0 = u2f2(acc2[i][0]);
        float2 p1 = u2f2(acc2[i][1]);
        float2 p2 = u2f2(acc2[i][2]);
        float2 p3 = u2f2(acc2[i][3]);
        float4 o0, o1;
        o0.x = p0.x + bias[n + 0]; o0.y = p0.y + bias[n + 1];
        o0.z = p1.x + bias[n + 2]; o0.w = p1.y + bias[n + 3];
        o1.x = p2.x + bias[n + 4]; o1.y = p2.y + bias[n + 5];
        o1.z = p3.x + bias[n + 6]; o1.w = p3.y + bias[n + 7];
        *(float4*)&C[m * 1024 + n] = o0;
        *(float4*)&C[m * 1024 + n + 4] = o1;
    }
}

// ---------------------------------------------------------------------------
// Transpose pre-activations: in[(t*32+b)*1024+n] -> out[(t*1024+n)*32+b]
// Grid (1024 t, 32 nchunk), block (32, 8). smem-tiled, coalesced both sides.
// ---------------------------------------------------------------------------
__global__ void transpose_pre(const float* __restrict__ in,
                              float* __restrict__ out) {
    __shared__ float tile[32][33];
    int t = blockIdx.x;
    int n0 = blockIdx.y * 32;
    int lx = threadIdx.x;
    int ly = threadIdx.y;
#pragma unroll
    for (int i = ly; i < 32; i += 8)
        tile[i][lx] = in[((size_t)t * 32 + i) * 1024 + n0 + lx];
    __syncthreads();
#pragma unroll
    for (int i = ly; i < 32; i += 8)
        out[((size_t)t * 1024 + n0 + i) * 32 + lx] = tile[lx][i];
}

// ---------------------------------------------------------------------------
// BiLSTM recurrence (one layer, both directions).
// 128 blocks x 128 threads. blocks [0,64): forward, [64,128): reverse.
// Block covers j in [jg*4, jg*4+4). Warp = jj (one j), lane = batch b (0..31).
// pre is TRANSPOSED [t][1024][32] -> prefetch = 4 coalesced LDG.32.
// h exchange via compact parity-double-buffered g_hx[dir][par][j][b]:
//   producers: one coalesced STG.32 per thread (lane=b).
//   repack: 16 fully-coalesced LDG.128 per thread, scatter STS into shh.
// hout [t][b][512] still written (staged, warp 0) for downstream kernels.
// Cross-block sync: monotone counter, red.release arrival + ld.acquire poll.
// ---------------------------------------------------------------------------
__global__ void __launch_bounds__(128) lstm_layer(const float* __restrict__ pret_fw,
                                                  const float* __restrict__ pret_rv,
                                                  const float* __restrict__ whh_fw,
                                                  const float* __restrict__ whh_rv,
                                                  float* __restrict__ hout) {
    extern __shared__ float smem[];
    float* sw = smem;                      // [jj*4+g][256]
    float* shh = smem + LSTM_SW_FLOATS;    // [b][268]
    float* snew = smem + LSTM_SN_OFF;      // [b*4 + jj]

    const int tid = threadIdx.x;
    const int dir = blockIdx.x >> 6;
    const int jg = blockIdx.x & 63;
    const int jj = tid >> 5;               // warp id = local j
    const int lane = tid & 31;             // lane = batch
    const int j = jg * 4 + jj;
    const float* whh = dir ? whh_rv : whh_fw;
    const float* pret = dir ? pret_rv : pret_fw;
    const int foff = dir ? 256 : 0;

    // Load W_hh slice: sw[(jj*4+g)*256 + k] = whh[(g*256 + j)*256 + k]
    for (int i = tid; i < 4096; i += 128) {
        int row = i >> 8;                  // jj*4+g
        int k = i & 255;
        int ljj = row >> 2, g = row & 3;
        sw[row * 256 + k] = whh[((size_t)(g * 256 + jg * 4 + ljj)) * 256 + k];
    }
    for (int i = tid; i < LSTM_SH_FLOATS; i += 128) shh[i] = 0.f;
    __syncthreads();

    const float* hrow = shh + lane * 268;
    const float* wbase = sw + jj * 1024;   // 4 gate rows x 256

    unsigned* cntp = dir ? &g_cnt_r[0] : &g_cnt_f[0];
    float* hx_dir = &g_hx[dir * 2 * 256 * 32];

    float c_state = 0.f;
    int t = dir ? (TCON - 1) : 0;

    // prefetch pre-activations for step 0 (coalesced: lane = b contiguous)
    {
        const float* pt = pret + ((size_t)t * 1024 + j) * 32 + lane;
        // gates at n = j, 256+j, 512+j, 768+j -> stride 256*32 floats
    }
    const float* pt0 = pret + ((size_t)t * 1024 + j) * 32 + lane;
    float p_i = pt0[0];
    float p_f = pt0[256 * 32];
    float p_g = pt0[512 * 32];
    float p_o = pt0[768 * 32];

    for (int step = 0; step < TCON; step++) {
        // ---- gate GEMV: acc[g] = sum_k W[g*256+j][k] * h[k][b] ----
        u64 a0 = 0ull, a1 = 0ull, a2 = 0ull, a3 = 0ull;
#pragma unroll 2
        for (int k4 = 0; k4 < 64; k4++) {
            ulonglong2 hv = *(const ulonglong2*)(hrow + k4 * 4);
            ulonglong2 w0 = *(const ulonglong2*)(wbase + k4 * 4);
            ulonglong2 w1 = *(const ulonglong2*)(wbase + 256 + k4 * 4);
            ulonglong2 w2 = *(const ulonglong2*)(wbase + 512 + k4 * 4);
            ulonglong2 w3 = *(const ulonglong2*)(wbase + 768 + k4 * 4);
            fma2(a0, w0.x, hv.x); fma2(a0, w0.y, hv.y);
            fma2(a1, w1.x, hv.x); fma2(a1, w1.y, hv.y);
            fma2(a2, w2.x, hv.x); fma2(a2, w2.y, hv.y);
            fma2(a3, w3.x, hv.x); fma2(a3, w3.y, hv.y);
        }
        float2 vi = u2f2(a0), vf = u2f2(a1), vg = u2f2(a2), vo = u2f2(a3);
        float gi = vi.x + vi.y + p_i;
        float gf = vf.x + vf.y + p_f;
        float gg = vg.x + vg.y + p_g;
        float go = vo.x + vo.y + p_o;
        float iv = sigf(gi), fv = sigf(gf), zv = tanh_fast(gg), ov = sigf(go);
        c_state = fv * c_state + iv * zv;
        float h_val = ov * tanh_fast(c_state);

        // publish h into the compact exchange buffer (coalesced STG.32)
        hx_dir[((step & 1) * 256 + j) * 32 + lane] = h_val;
        // stage for the hout writer
        snew[lane * 4 + jj] = h_val;

        int t_next = dir ? (t - 1) : (t + 1);
        if (step != TCON - 1) {
            // prefetch next step's pre-activations (coalesced, off-chain)
            const float* ptn = pret + ((size_t)t_next * 1024 + j) * 32 + lane;
            p_i = ptn[0];
            p_f = ptn[256 * 32];
            p_g = ptn[512 * 32];
            p_o = ptn[768 * 32];
        }

        __syncthreads();                 // hx + snew stores issued block-wide

        // ---- hout store (warp 0) + barrier ----
        if (jj == 0) {
            float4 hv4 = *(const float4*)(snew + lane * 4);
            *(float4*)&hout[((size_t)t * 32 + lane) * 512 + foff + jg * 4] = hv4;
            __syncwarp();
            if (lane == 0) {
                red_rel_add(cntp, 1u);   // publishes hx stores (cumulative rel)
                unsigned target = 64u * (unsigned)(step + 1);
                while (ld_acq(cntp) < target) {}
            }
        }
        __syncthreads();

        // ---- repack h_t from compact exchange (fully coalesced loads) ----
        if (step != TCON - 1) {
            const float4* s4 = (const float4*)(hx_dir + (step & 1) * 256 * 32);
            float4 tmp[16];
#pragma unroll
            for (int q = 0; q < 16; q++) tmp[q] = s4[q * 128 + tid];
#pragma unroll
            for (int q = 0; q < 16; q++) {
                int f = q * 128 + tid;
                int k = f >> 3;
                int b0 = (f & 7) * 4;
                shh[(b0 + 0) * 268 + k] = tmp[q].x;
                shh[(b0 + 1) * 268 + k] = tmp[q].y;
                shh[(b0 + 2) * 268 + k] = tmp[q].z;
                shh[(b0 + 3) * 268 + k] = tmp[q].w;
            }
        }
        __syncthreads();
        t = t_next;
    }

    // ---- epilogue: one-shot reset of counters for next launch / replay ----
    if (tid == 0) {
        unsigned old = atom_inc_acqrel(&g_ecnt[0]);
        if (old == 127u) {
            st_rlx(&g_cnt_f[0], 0u);
            st_rlx(&g_cnt_r[0], 0u);
            st_rlx(&g_ecnt[0], 0u);
        }
    }
}

// ---------------------------------------------------------------------------
// FC heads (split-k partials + deterministic reduce)
// ---------------------------------------------------------------------------
__global__ void __launch_bounds__(256) fc_main(const float* __restrict__ h,
                                               const float* __restrict__ w1,
                                               const float* __restrict__ w2) {
    extern __shared__ float sh[];
    int kc = blockIdx.x;
    int grp = blockIdx.y;
    int tid = threadIdx.x;
    int nl = tid >> 4, bb = tid & 15;
    int n = grp * 16 + nl;
    bool valid = (n < 190);
    const float* wrow = valid
        ? (n < 100 ? w1 + (size_t)n * 524288 : w2 + (size_t)(n - 100) * 524288)
        : w1;

    float ax = 0.f, ay = 0.f;
    for (int tt = 0; tt < 32; tt++) {
        int t = kc * 32 + tt;
        const float* slab = h + (size_t)t * 16384;
        __syncthreads();
        for (int i = tid; i < 4096; i += 256) {
            int b = i >> 7;
            int q = i & 127;
            float4 v = *(const float4*)&slab[b * 512 + q * 4];
            int bl = (b & 15) * 2 + (b >> 4);
            int f = q * 4;
            sh[(f + 0) * 32 + bl] = v.x;
            sh[(f + 1) * 32 + bl] = v.y;
            sh[(f + 2) * 32 + bl] = v.z;
            sh[(f + 3) * 32 + bl] = v.w;
        }
        __syncthreads();
        const float* wp = wrow + (size_t)t * 512;
#pragma unroll 4
        for (int f4 = 0; f4 < 128; f4++) {
            float4 wv = *(const float4*)(wp + f4 * 4);
            const float* s0 = sh + (f4 * 4) * 32 + bb * 2;
            float2 a0 = *(const float2*)(s0);
            float2 a1 = *(const float2*)(s0 + 32);
            float2 a2 = *(const float2*)(s0 + 64);
            float2 a3 = *(const float2*)(s0 + 96);
            ax = fmaf(wv.x, a0.x, ax); ay = fmaf(wv.x, a0.y, ay);
            ax = fmaf(wv.y, a1.x, ax); ay = fmaf(wv.y, a1.y, ay);
            ax = fmaf(wv.z, a2.x, ax); ay = fmaf(wv.z, a2.y, ay);
            ax = fmaf(wv.w, a3.x, ax); ay = fmaf(wv.w, a3.y, ay);
        }
    }
    if (valid) {
        g_fc_part[((size_t)kc * 192 + n) * 32 + bb] = ax;
        g_fc_part[((size_t)kc * 192 + n) * 32 + bb + 16] = ay;
    }
}

__global__ void fc_reduce(const float* __restrict__ b1,
                          const float* __restrict__ b2,
                          float* __restrict__ out) {
    int i = blockIdx.x * 256 + threadIdx.x;
    if (i >= 6080) return;
    int n = i >> 5;
    int b = i & 31;
    float s = (n < 100) ? b1[n] : b2[n - 100];
#pragma unroll
    for (int kc = 0; kc < 32; kc++)
        s += g_fc_part[((size_t)kc * 192 + n) * 32 + b];
    if (n < 100) out[b * 100 + n] = s;
    else out[3200 + b * 90 + (n - 100)] = s;
}

// ---------------------------------------------------------------------------
// Launch
// ---------------------------------------------------------------------------
extern "C" void kernel_launch(void* const* d_in, const int* in_sizes, int n_in,
                              void* d_out, int out_size) {
    const float* x       = (const float*)d_in[0];
    const float* conv_w  = (const float*)d_in[1];
    const float* conv_b  = (const float*)d_in[2];
    const float* bn_g    = (const float*)d_in[3];
    const float* bn_b    = (const float*)d_in[4];
    const float* bn_m    = (const float*)d_in[5];
    const float* bn_v    = (const float*)d_in[6];
    const float* w_ih_f0 = (const float*)d_in[7];
    const float* w_hh_f0 = (const float*)d_in[8];
    const float* b_f0    = (const float*)d_in[9];
    const float* w_ih_r0 = (const float*)d_in[10];
    const float* w_hh_r0 = (const float*)d_in[11];
    const float* b_r0    = (const float*)d_in[12];
    const float* w_ih_f1 = (const float*)d_in[13];
    const float* w_hh_f1 = (const float*)d_in[14];
    const float* b_f1    = (const float*)d_in[15];
    const float* w_ih_r1 = (const float*)d_in[16];
    const float* w_hh_r1 = (const float*)d_in[17];
    const float* b_r1    = (const float*)d_in[18];
    const float* fc1_w   = (const float*)d_in[19];
    const float* fc1_b   = (const float*)d_in[20];
    const float* fc2_w   = (const float*)d_in[21];
    const float* fc2_b   = (const float*)d_in[22];
    float* out = (float*)d_out;

    float *py, *ppf, *ppr, *ptf, *ptr, *ph0, *ph1;
    cudaGetSymbolAddress((void**)&py, g_y);
    cudaGetSymbolAddress((void**)&ppf, g_pre_f);
    cudaGetSymbolAddress((void**)&ppr, g_pre_r);
    cudaGetSymbolAddress((void**)&ptf, g_pret_f);
    cudaGetSymbolAddress((void**)&ptr, g_pret_r);
    cudaGetSymbolAddress((void**)&ph0, g_h0);
    cudaGetSymbolAddress((void**)&ph1, g_h1);

    cudaFuncSetAttribute(lstm_layer, cudaFuncAttributeMaxDynamicSharedMemorySize, LSTM_SMEM);
    cudaFuncSetAttribute(fc_main, cudaFuncAttributeMaxDynamicSharedMemorySize, 65536);

    dim3 tg(1024, 32), tb(32, 8);

    // 1) conv + bn + relu
    conv_bn<<<32768, 256>>>(x, conv_w, conv_b, bn_g, bn_b, bn_m, bn_v);

    // 2) layer 0 input projections (K=256) + transpose
    dim3 gg(8, 256);
    sgemm_tn<<<gg, 256>>>(py, w_ih_f0, b_f0, ppf, 256);
    sgemm_tn<<<gg, 256>>>(py, w_ih_r0, b_r0, ppr, 256);
    transpose_pre<<<tg, tb>>>(ppf, ptf);
    transpose_pre<<<tg, tb>>>(ppr, ptr);

    // 3) layer 0 recurrence
    lstm_layer<<<128, 128, LSTM_SMEM>>>(ptf, ptr, w_hh_f0, w_hh_r0, ph0);

    // 4) layer 1 input projections (K=512) + transpose
    sgemm_tn<<<gg, 256>>>(ph0, w_ih_f1, b_f1, ppf, 512);
    sgemm_tn<<<gg, 256>>>(ph0, w_ih_r1, b_r1, ppr, 512);
    transpose_pre<<<tg, tb>>>(ppf, ptf);
    transpose_pre<<<tg, tb>>>(ppr, ptr);

    // 5) layer 1 recurrence
    lstm_layer<<<128, 128, LSTM_SMEM>>>(ptf, ptr, w_hh_f1, w_hh_r1, ph1);

    // 6) FC heads
    dim3 fg(32, 12);
    fc_main<<<fg, 256, 65536>>>(ph1, fc1_w, fc2_w);
    fc_reduce<<<24, 256>>>(fc1_b, fc2_b, out);
}